// round 1
// baseline (speedup 1.0000x reference)
#include <cuda_runtime.h>

#define N_TOTAL   16384
#define GRID_MAIN 444
#define TPB       256
#define CTPB      1024

__device__ float g_pos[N_TOTAL];
__device__ float g_neg[N_TOTAL];
__device__ int   g_npos;
__device__ int   g_nneg;
__device__ float g_partial[GRID_MAIN];

__device__ __forceinline__ float neg_inf() { return __int_as_float(0xff800000); }

// ---------------------------------------------------------------------------
// Kernel 1: deterministic compaction of pos/neg scores (block-wide scan,
// no atomics -> output ordering is fixed, so downstream float sums are
// bit-reproducible across replays).
// ---------------------------------------------------------------------------
__global__ __launch_bounds__(CTPB)
void compact_kernel(const int* __restrict__ yt, const float* __restrict__ yp) {
    const int tid   = threadIdx.x;
    const int CHUNK = N_TOTAL / CTPB;   // 16 contiguous elements per thread
    const int base  = tid * CHUNK;

    int   cls[CHUNK];
    float vals[CHUNK];
    int cp = 0;
    #pragma unroll
    for (int k = 0; k < CHUNK; k++) {
        cls[k]  = yt[base + k];
        vals[k] = yp[base + k];
        cp += (cls[k] == 1);
    }

    // block exclusive scan of cp (every element is pos or neg, so
    // neg offset = base - pos_exclusive)
    const int lane = tid & 31, warp = tid >> 5;
    int inc = cp;
    #pragma unroll
    for (int o = 1; o < 32; o <<= 1) {
        int t = __shfl_up_sync(0xffffffffu, inc, o);
        if (lane >= o) inc += t;
    }
    __shared__ int wsum[32];
    if (lane == 31) wsum[warp] = inc;
    __syncthreads();
    if (warp == 0) {
        int w = wsum[lane];
        #pragma unroll
        for (int o = 1; o < 32; o <<= 1) {
            int t = __shfl_up_sync(0xffffffffu, w, o);
            if (lane >= o) w += t;
        }
        wsum[lane] = w;
    }
    __syncthreads();

    const int excl = inc - cp + (warp > 0 ? wsum[warp - 1] : 0);
    int po = excl;
    int no = base - excl;
    #pragma unroll
    for (int k = 0; k < CHUNK; k++) {
        if (cls[k] == 1) g_pos[po++] = vals[k];
        else             g_neg[no++] = vals[k];
    }
    if (tid == CTPB - 1) {
        g_npos = excl + cp;
        g_nneg = N_TOTAL - (excl + cp);
    }
}

// ---------------------------------------------------------------------------
// Kernel 2: pairwise hinge sum. Negs staged in smem (padded with -inf to a
// multiple of 4*TPB so the inner loop is a pure float4 stream). 4 pos rows
// per j-load amortize the LDS and give ILP on the fma pipe.
// ---------------------------------------------------------------------------
__global__ __launch_bounds__(TPB)
void main_kernel() {
    extern __shared__ float sneg[];
    const int tid  = threadIdx.x;
    const int nneg = g_nneg;
    const int npos = g_npos;
    const int nneg_pad = (nneg + 4 * TPB - 1) & ~(4 * TPB - 1);

    for (int j = tid;        j < nneg;     j += TPB) sneg[j] = g_neg[j];
    for (int j = nneg + tid; j < nneg_pad; j += TPB) sneg[j] = neg_inf();
    __syncthreads();

    float a0 = 0.f, a1 = 0.f, a2 = 0.f, a3 = 0.f;

    for (int r0 = blockIdx.x * 4; r0 < npos; r0 += GRID_MAIN * 4) {
        // -inf sentinel rows contribute exactly 0 through max(0, -inf + n)
        const float c0 = (r0 + 0 < npos) ? (1.0f - g_pos[r0 + 0]) : neg_inf();
        const float c1 = (r0 + 1 < npos) ? (1.0f - g_pos[r0 + 1]) : neg_inf();
        const float c2 = (r0 + 2 < npos) ? (1.0f - g_pos[r0 + 2]) : neg_inf();
        const float c3 = (r0 + 3 < npos) ? (1.0f - g_pos[r0 + 3]) : neg_inf();

        for (int j = tid * 4; j < nneg_pad; j += TPB * 4) {
            const float4 nv = *reinterpret_cast<const float4*>(&sneg[j]);
            a0 += fmaxf(0.f, c0 + nv.x); a0 += fmaxf(0.f, c0 + nv.y);
            a0 += fmaxf(0.f, c0 + nv.z); a0 += fmaxf(0.f, c0 + nv.w);
            a1 += fmaxf(0.f, c1 + nv.x); a1 += fmaxf(0.f, c1 + nv.y);
            a1 += fmaxf(0.f, c1 + nv.z); a1 += fmaxf(0.f, c1 + nv.w);
            a2 += fmaxf(0.f, c2 + nv.x); a2 += fmaxf(0.f, c2 + nv.y);
            a2 += fmaxf(0.f, c2 + nv.z); a2 += fmaxf(0.f, c2 + nv.w);
            a3 += fmaxf(0.f, c3 + nv.x); a3 += fmaxf(0.f, c3 + nv.y);
            a3 += fmaxf(0.f, c3 + nv.z); a3 += fmaxf(0.f, c3 + nv.w);
        }
    }

    float acc = (a0 + a1) + (a2 + a3);

    __syncthreads();              // smem reuse for block reduce
    sneg[tid] = acc;
    __syncthreads();
    #pragma unroll
    for (int s = TPB / 2; s > 0; s >>= 1) {
        if (tid < s) sneg[tid] += sneg[tid + s];
        __syncthreads();
    }
    if (tid == 0) g_partial[blockIdx.x] = sneg[0];
}

// ---------------------------------------------------------------------------
// Kernel 3: final reduction (double precision) + denom.
// ---------------------------------------------------------------------------
__global__ __launch_bounds__(256)
void finalize_kernel(float* __restrict__ out) {
    __shared__ double sd[256];
    double s = 0.0;
    for (int i = threadIdx.x; i < GRID_MAIN; i += 256) s += (double)g_partial[i];
    sd[threadIdx.x] = s;
    __syncthreads();
    #pragma unroll
    for (int st = 128; st > 0; st >>= 1) {
        if (threadIdx.x < st) sd[threadIdx.x] += sd[threadIdx.x + st];
        __syncthreads();
    }
    if (threadIdx.x == 0) {
        const double denom = (double)g_npos * (double)g_nneg;
        out[0] = (float)(sd[0] / denom);
    }
}

extern "C" void kernel_launch(void* const* d_in, const int* in_sizes, int n_in,
                              void* d_out, int out_size) {
    const int*   yt = (const int*)d_in[0];
    const float* yp = (const float*)d_in[1];

    // 64 KB dynamic smem opt-in (idempotent; not a stream op, capture-safe)
    cudaFuncSetAttribute(main_kernel,
                         cudaFuncAttributeMaxDynamicSharedMemorySize, 65536);

    compact_kernel<<<1, CTPB>>>(yt, yp);
    main_kernel<<<GRID_MAIN, TPB, 65536>>>();
    finalize_kernel<<<1, 256>>>((float*)d_out);
}

// round 2
// speedup vs baseline: 1.6884x; 1.6884x over previous
#include <cuda_runtime.h>

#define N_TOTAL 16384
#define TPB     512
#define GRID    148
#define ROWS    4      // pos rows per outer iteration
#define JV      8      // negs per thread per inner iteration (two float4)

__device__ float        g_partial[GRID];
__device__ unsigned int g_arrive = 0;   // reset by last block every launch

__device__ __forceinline__ float neg_inf() { return __int_as_float(0xff800000); }

// ---- packed f32x2 helpers (sm_103a) -------------------------------------
__device__ __forceinline__ unsigned long long pk(float lo, float hi) {
    unsigned long long r;
    asm("mov.b64 %0, {%1,%2};" : "=l"(r) : "f"(lo), "f"(hi));
    return r;
}
__device__ __forceinline__ void upk(float& lo, float& hi, unsigned long long v) {
    asm("mov.b64 {%0,%1}, %2;" : "=f"(lo), "=f"(hi) : "l"(v));
}
__device__ __forceinline__ unsigned long long addx2(unsigned long long a,
                                                    unsigned long long b) {
    unsigned long long r;
    asm("add.rn.f32x2 %0, %1, %2;" : "=l"(r) : "l"(a), "l"(b));
    return r;
}
// acc += max(0, c+n) on two lanes: FADD2 + 2x FMNMX + FADD2  (2 instr/pair)
__device__ __forceinline__ unsigned long long hinge2(unsigned long long acc,
                                                     unsigned long long c2,
                                                     unsigned long long n2) {
    unsigned long long t = addx2(c2, n2);
    float f0, f1;
    upk(f0, f1, t);
    return addx2(acc, pk(fmaxf(f0, 0.f), fmaxf(f1, 0.f)));
}

// ---------------------------------------------------------------------------
// One fused persistent kernel: per-block deterministic compaction into smem,
// pairwise hinge sum, in-kernel final reduction by the last block.
// ---------------------------------------------------------------------------
__global__ __launch_bounds__(TPB)
void fused_kernel(const int* __restrict__ yt, const float* __restrict__ yp,
                  float* __restrict__ out) {
    extern __shared__ float sm[];      // [0,nneg_pad): negs; then [npos): pos
    __shared__ int   wsum[16];
    __shared__ int   s_amlast;
    __shared__ float s_red[16];

    const int tid  = threadIdx.x;
    const int lane = tid & 31;
    const int warp = tid >> 5;

    // ---- pass 1: per-thread pos count over 32 contiguous elements ----
    const int E    = N_TOTAL / TPB;    // 32
    const int base = tid * E;
    int cp = 0;
    #pragma unroll
    for (int k = 0; k < E / 4; k++) {
        int4 t = ((const int4*)yt)[(base >> 2) + k];
        cp += (t.x == 1) + (t.y == 1) + (t.z == 1) + (t.w == 1);
    }

    // ---- block exclusive scan (deterministic) ----
    int inc = cp;
    #pragma unroll
    for (int o = 1; o < 32; o <<= 1) {
        int t = __shfl_up_sync(0xffffffffu, inc, o);
        if (lane >= o) inc += t;
    }
    if (lane == 31) wsum[warp] = inc;
    __syncthreads();
    if (warp == 0) {
        int w = (lane < 16) ? wsum[lane] : 0;
        #pragma unroll
        for (int o = 1; o < 16; o <<= 1) {
            int t = __shfl_up_sync(0xffffffffu, w, o);
            if (lane >= o) w += t;
        }
        if (lane < 16) wsum[lane] = w;
    }
    __syncthreads();

    const int excl = inc - cp + (warp > 0 ? wsum[warp - 1] : 0);
    const int npos = wsum[15];
    const int nneg = N_TOTAL - npos;
    const int nneg_pad = (nneg + 7) & ~7;          // pad only to JV multiple
    float* sneg = sm;
    float* spos = sm + nneg_pad;

    // ---- pass 2: scatter into smem (pos/neg compacted); pad with -inf ----
    {
        int po = excl;
        int no = base - excl;
        #pragma unroll
        for (int k = 0; k < E / 4; k++) {
            int4   t = ((const int4*)yt)[(base >> 2) + k];
            float4 v = ((const float4*)yp)[(base >> 2) + k];
            if (t.x == 1) spos[po++] = v.x; else sneg[no++] = v.x;
            if (t.y == 1) spos[po++] = v.y; else sneg[no++] = v.y;
            if (t.z == 1) spos[po++] = v.z; else sneg[no++] = v.z;
            if (t.w == 1) spos[po++] = v.w; else sneg[no++] = v.w;
        }
        for (int j = nneg + tid; j < nneg_pad; j += TPB) sneg[j] = neg_inf();
    }
    __syncthreads();

    // ---- main pairwise hinge loop ----
    unsigned long long acc[ROWS];
    #pragma unroll
    for (int r = 0; r < ROWS; r++) acc[r] = pk(0.f, 0.f);

    for (int r0 = blockIdx.x * ROWS; r0 < npos; r0 += GRID * ROWS) {
        unsigned long long c2[ROWS];
        #pragma unroll
        for (int r = 0; r < ROWS; r++) {
            float c = (r0 + r < npos) ? (1.0f - spos[r0 + r]) : neg_inf();
            c2[r] = pk(c, c);
        }
        for (int j = tid * JV; j < nneg_pad; j += TPB * JV) {
            const float4 A = *reinterpret_cast<const float4*>(sneg + j);
            const float4 B = *reinterpret_cast<const float4*>(sneg + j + 4);
            const unsigned long long n0 = pk(A.x, A.y), n1 = pk(A.z, A.w);
            const unsigned long long n2 = pk(B.x, B.y), n3 = pk(B.z, B.w);
            #pragma unroll
            for (int r = 0; r < ROWS; r++) {
                acc[r] = hinge2(acc[r], c2[r], n0);
                acc[r] = hinge2(acc[r], c2[r], n1);
                acc[r] = hinge2(acc[r], c2[r], n2);
                acc[r] = hinge2(acc[r], c2[r], n3);
            }
        }
    }

    // ---- block reduction (fixed order -> deterministic) ----
    float tsum = 0.f;
    #pragma unroll
    for (int r = 0; r < ROWS; r++) {
        float lo, hi;
        upk(lo, hi, acc[r]);
        tsum += lo + hi;
    }
    #pragma unroll
    for (int o = 16; o > 0; o >>= 1)
        tsum += __shfl_down_sync(0xffffffffu, tsum, o);
    if (lane == 0) s_red[warp] = tsum;
    __syncthreads();
    if (warp == 0) {
        float w = (lane < 16) ? s_red[lane] : 0.f;
        #pragma unroll
        for (int o = 16; o > 0; o >>= 1)
            w += __shfl_down_sync(0xffffffffu, w, o);
        if (lane == 0) g_partial[blockIdx.x] = w;
    }

    // ---- last block finalizes (deterministic fixed-order double sum) ----
    if (tid == 0) {
        __threadfence();
        unsigned int prev = atomicAdd(&g_arrive, 1u);
        s_amlast = (prev == GRID - 1);
    }
    __syncthreads();
    if (s_amlast && warp == 0) {
        __threadfence();
        double s = 0.0;
        for (int i = lane; i < GRID; i += 32) s += (double)g_partial[i];
        #pragma unroll
        for (int o = 16; o > 0; o >>= 1)
            s += __shfl_down_sync(0xffffffffu, s, o);
        if (lane == 0) {
            const double denom = (double)npos * (double)nneg;
            out[0] = (float)(s / denom);
            g_arrive = 0u;   // reset for next graph replay
        }
    }
}

extern "C" void kernel_launch(void* const* d_in, const int* in_sizes, int n_in,
                              void* d_out, int out_size) {
    const int*   yt = (const int*)d_in[0];
    const float* yp = (const float*)d_in[1];

    const int smem_bytes = (N_TOTAL + 16) * sizeof(float);   // ~65.6 KB
    cudaFuncSetAttribute(fused_kernel,
                         cudaFuncAttributeMaxDynamicSharedMemorySize, smem_bytes);

    fused_kernel<<<GRID, TPB, smem_bytes>>>(yt, yp, (float*)d_out);
}